// round 1
// baseline (speedup 1.0000x reference)
#include <cuda_runtime.h>
#include <math.h>

// ---------------- problem constants ----------------
constexpr int B_ = 2, T_ = 1024, D_ = 768, H_ = 12, L_ = 4, E_ = 8, DFF_ = 3072, V_ = 32000;
constexpr int HEAD_ = D_ / H_;       // 64
constexpr int D3_ = 3 * D_;          // 2304
constexpr int M_ = B_ * T_;          // 2048 tokens

// ---------------- scratch (static device, allocation-free) ----------------
__device__ __align__(128) float g_x[(size_t)M_ * D_];
__device__ __align__(128) float g_h[(size_t)M_ * D_];
__device__ __align__(128) float g_attn[(size_t)M_ * D_];
__device__ __align__(128) float g_qkv[(size_t)M_ * D3_];
__device__ __align__(128) float g_scores[(size_t)B_ * H_ * T_ * T_];   // ~100 MB
__device__ __align__(128) float g_hid[(size_t)M_ * E_ * DFF_];         // ~201 MB
__device__ __align__(128) float g_mp[(size_t)M_ * E_];

// ---------------- reductions ----------------
__device__ __forceinline__ float bsum(float v, float* sred) {
#pragma unroll
    for (int o = 16; o; o >>= 1) v += __shfl_xor_sync(0xffffffffu, v, o);
    if ((threadIdx.x & 31) == 0) sred[threadIdx.x >> 5] = v;
    __syncthreads();
    float r = 0.f;
#pragma unroll
    for (int i = 0; i < 8; i++) r += sred[i];
    __syncthreads();
    return r;
}
__device__ __forceinline__ float bmax(float v, float* sred) {
#pragma unroll
    for (int o = 16; o; o >>= 1) v = fmaxf(v, __shfl_xor_sync(0xffffffffu, v, o));
    if ((threadIdx.x & 31) == 0) sred[threadIdx.x >> 5] = v;
    __syncthreads();
    float r = -3.402823e38f;
#pragma unroll
    for (int i = 0; i < 8; i++) r = fmaxf(r, sred[i]);
    __syncthreads();
    return r;
}

// ---------------- generic tiled GEMM ----------------
// C[m,n] (op)= epilogue( sum_k A[m*lda+k] * B(n,k) )
// BNT=true : B(n,k) = Bw[(k/KB)*expStride + n*ldb + (k%KB)]   (row-major [N,K], optional expert-K blocks)
// BNT=false: B(n,k) = Bw[k*ldb + n]                           (row-major [K,N])
// MODE 0: C = alpha*acc     MODE 1: C = scale[m*E + n/DFF]*relu(acc)     MODE 2: C += acc
template <int MODE, bool BNT>
__global__ void __launch_bounds__(256)
gemm_tile(const float* __restrict__ A, const float* __restrict__ Bw,
          float* __restrict__ C, const float* __restrict__ scale,
          int M, int N, int K, int lda, int ldb, int ldc,
          long expStride, int KB, int ZH,
          long sAb, long sAh, long sBb, long sBh, long sCb, long sCh,
          float alpha, int causalSkip, int causalK)
{
    constexpr int BM = 128, BN = 128, BK = 16;
    if (ZH > 0) {
        int z = blockIdx.z;
        int zb = z / ZH, zh = z - zb * ZH;
        A  += zb * sAb + zh * sAh;
        Bw += zb * sBb + zh * sBh;
        C  += zb * sCb + zh * sCh;
    }
    const int n0 = blockIdx.x * BN;
    const int m0 = blockIdx.y * BM;
    if (causalSkip && n0 > m0) return;                 // tile fully above causal diagonal
    const int kend = causalK ? min(K, m0 + BM) : K;    // multiple of BK

    __shared__ float As[BK][BM];
    __shared__ float Bs[BK][BN];

    const int tid  = threadIdx.x;
    const int trow = (tid >> 4) << 3;   // m within tile
    const int tcol = (tid & 15) << 3;   // n within tile

    float acc[8][8];
#pragma unroll
    for (int i = 0; i < 8; i++)
#pragma unroll
        for (int j = 0; j < 8; j++) acc[i][j] = 0.f;

    for (int k0 = 0; k0 < kend; k0 += BK) {
        // ---- A tile (BMxBK), transpose into As[k][m]
#pragma unroll
        for (int it = 0; it < 2; it++) {
            int idx = tid + it * 256;
            int r = idx >> 2;
            int c4 = (idx & 3) << 2;
            float4 v = *(const float4*)(A + (long)(m0 + r) * lda + k0 + c4);
            As[c4 + 0][r] = v.x; As[c4 + 1][r] = v.y;
            As[c4 + 2][r] = v.z; As[c4 + 3][r] = v.w;
        }
        // ---- B tile
        if (BNT) {
            int e = k0 / KB;
            const float* Bb = Bw + (long)e * expStride + (k0 - e * KB);
#pragma unroll
            for (int it = 0; it < 2; it++) {
                int idx = tid + it * 256;
                int r = idx >> 2;
                int c4 = (idx & 3) << 2;
                float4 v = make_float4(0.f, 0.f, 0.f, 0.f);
                if (n0 + r < N) v = *(const float4*)(Bb + (long)(n0 + r) * ldb + c4);
                Bs[c4 + 0][r] = v.x; Bs[c4 + 1][r] = v.y;
                Bs[c4 + 2][r] = v.z; Bs[c4 + 3][r] = v.w;
            }
        } else {
#pragma unroll
            for (int it = 0; it < 2; it++) {
                int idx = tid + it * 256;
                int r = idx >> 5;            // k
                int c4 = (idx & 31) << 2;    // n
                float4 v = make_float4(0.f, 0.f, 0.f, 0.f);
                if (n0 + c4 + 3 < N) v = *(const float4*)(Bw + (long)(k0 + r) * ldb + n0 + c4);
                *(float4*)&Bs[r][c4] = v;
            }
        }
        __syncthreads();
#pragma unroll
        for (int kk = 0; kk < BK; kk++) {
            float ra[8], rb[8];
#pragma unroll
            for (int i = 0; i < 8; i++) ra[i] = As[kk][trow + i];
#pragma unroll
            for (int j = 0; j < 8; j++) rb[j] = Bs[kk][tcol + j];
#pragma unroll
            for (int i = 0; i < 8; i++)
#pragma unroll
                for (int j = 0; j < 8; j++)
                    acc[i][j] = fmaf(ra[i], rb[j], acc[i][j]);
        }
        __syncthreads();
    }

#pragma unroll
    for (int i = 0; i < 8; i++) {
        int m = m0 + trow + i;
        if (m >= M) continue;
#pragma unroll
        for (int j = 0; j < 8; j++) {
            int n = n0 + tcol + j;
            if (n >= N) continue;
            long ci = (long)m * ldc + n;
            float v = acc[i][j];
            if (MODE == 0)      C[ci] = alpha * v;
            else if (MODE == 1) C[ci] = scale[(long)m * E_ + (n / DFF_)] * fmaxf(v, 0.f);
            else                C[ci] += v;
        }
    }
}

// ---------------- embedding + LN0 ----------------
__global__ void embed_ln_kernel(const int* __restrict__ tokens,
                                const float* __restrict__ wte, const float* __restrict__ wpe,
                                const float* __restrict__ g, const float* __restrict__ b,
                                float* __restrict__ y)
{
    __shared__ float sred[8];
    long row = blockIdx.x;                  // b*T + t
    int t = (int)(row % T_);
    int tok = tokens[row];
    const float* we = wte + (long)tok * D_;
    const float* pe = wpe + (long)t * D_;
    float* yr = y + row * D_;
    int tid = threadIdx.x;
    float v[3], s = 0.f;
#pragma unroll
    for (int i = 0; i < 3; i++) { int c = tid + i * 256; v[i] = we[c] + pe[c]; s += v[i]; }
    s = bsum(s, sred);
    float mu = s * (1.f / D_);
    float q = 0.f;
#pragma unroll
    for (int i = 0; i < 3; i++) { float d = v[i] - mu; q += d * d; }
    q = bsum(q, sred);
    float rstd = rsqrtf(q * (1.f / D_) + 1e-5f);
#pragma unroll
    for (int i = 0; i < 3; i++) { int c = tid + i * 256; yr[c] = (v[i] - mu) * rstd * g[c] + b[c]; }
}

// ---------------- LayerNorm ----------------
__global__ void ln_kernel(const float* __restrict__ x, float* __restrict__ y,
                          const float* __restrict__ g, const float* __restrict__ b)
{
    __shared__ float sred[8];
    long row = blockIdx.x;
    const float* xr = x + row * D_;
    float* yr = y + row * D_;
    int tid = threadIdx.x;
    float v[3], s = 0.f;
#pragma unroll
    for (int i = 0; i < 3; i++) { v[i] = xr[tid + i * 256]; s += v[i]; }
    s = bsum(s, sred);
    float mu = s * (1.f / D_);
    float q = 0.f;
#pragma unroll
    for (int i = 0; i < 3; i++) { float d = v[i] - mu; q += d * d; }
    q = bsum(q, sred);
    float rstd = rsqrtf(q * (1.f / D_) + 1e-5f);
#pragma unroll
    for (int i = 0; i < 3; i++) { int c = tid + i * 256; yr[c] = (v[i] - mu) * rstd * g[c] + b[c]; }
}

// ---------------- causal softmax (in place on scores rows) ----------------
__global__ void softmax_kernel(float* __restrict__ sc)
{
    __shared__ float sred[8];
    long row = blockIdx.x;                   // z*T + i
    int i = (int)(row & (T_ - 1));
    float* r = sc + row * (long)T_;
    int tid = threadIdx.x;
    int n = i + 1;
    float rv[4];
    float mx = -3.402823e38f;
#pragma unroll
    for (int p = 0; p < 4; p++) { int j = tid + p * 256; if (j < n) { rv[p] = r[j]; mx = fmaxf(mx, rv[p]); } }
    mx = bmax(mx, sred);
    float s = 0.f;
#pragma unroll
    for (int p = 0; p < 4; p++) { int j = tid + p * 256; if (j < n) { rv[p] = __expf(rv[p] - mx); s += rv[p]; } }
    s = bsum(s, sred);
    float inv = 1.f / s;
    int zend = ((i >> 7) + 1) << 7;          // zero only up to tile boundary (PV truncates K there)
#pragma unroll
    for (int p = 0; p < 4; p++) {
        int j = tid + p * 256;
        if (j < n) r[j] = rv[p] * inv;
        else if (j < zend) r[j] = 0.f;
    }
}

// ---------------- router: scores, softmax, top-2, renorm ----------------
__global__ void router_kernel(const float* __restrict__ h, const float* __restrict__ rw,
                              float* __restrict__ mp)
{
    __shared__ float sc[E_];
    long tok = blockIdx.x;
    int tid = threadIdx.x;
    int w = tid >> 5, lane = tid & 31;
    const float* hr = h + tok * D_;
    const float* we = rw + (long)w * D_;     // 8 warps -> 8 experts
    float s = 0.f;
    for (int k = lane; k < D_; k += 32) s += hr[k] * we[k];
#pragma unroll
    for (int o = 16; o; o >>= 1) s += __shfl_xor_sync(0xffffffffu, s, o);
    if (lane == 0) sc[w] = s;
    __syncthreads();
    if (tid == 0) {
        float mx = sc[0];
#pragma unroll
        for (int e = 1; e < E_; e++) mx = fmaxf(mx, sc[e]);
        float p[E_], sum = 0.f;
#pragma unroll
        for (int e = 0; e < E_; e++) { p[e] = __expf(sc[e] - mx); sum += p[e]; }
        int i1 = 0;
#pragma unroll
        for (int e = 1; e < E_; e++) if (sc[e] > sc[i1]) i1 = e;
        int i2 = -1;
#pragma unroll
        for (int e = 0; e < E_; e++) if (e != i1 && (i2 < 0 || sc[e] > sc[i2])) i2 = e;
        float p1 = p[i1] / sum, p2 = p[i2] / sum;
        float inv = 1.f / (p1 + p2 + 1e-8f);
#pragma unroll
        for (int e = 0; e < E_; e++) mp[tok * E_ + e] = 0.f;
        mp[tok * E_ + i1] = p1 * inv;
        mp[tok * E_ + i2] = p2 * inv;
    }
}

// ---------------- host side ----------------
static float* sym(const void* s) { void* p = nullptr; cudaGetSymbolAddress(&p, s); return (float*)p; }

template <int MODE>
static void gemm_nt(const float* A, const float* Bw, float* C, const float* scale,
                    int M, int N, int K, int lda, int ldb, int ldc,
                    long expStride, int KB, float alpha = 1.f)
{
    dim3 grid((N + 127) / 128, (M + 127) / 128, 1);
    gemm_tile<MODE, true><<<grid, 256>>>(A, Bw, C, scale, M, N, K, lda, ldb, ldc,
                                         expStride, KB, 0, 0, 0, 0, 0, 0, 0,
                                         alpha, 0, 0);
}

extern "C" void kernel_launch(void* const* d_in, const int* in_sizes, int n_in,
                              void* d_out, int out_size)
{
    const int*   tokens  = (const int*)d_in[0];
    const float* wte     = (const float*)d_in[1];
    const float* wpe     = (const float*)d_in[2];
    const float* n0g     = (const float*)d_in[3];
    const float* n0b     = (const float*)d_in[4];
    const float* n1g     = (const float*)d_in[5];
    const float* n1b     = (const float*)d_in[6];
    const float* n2g     = (const float*)d_in[7];
    const float* n2b     = (const float*)d_in[8];
    const float* qkvw    = (const float*)d_in[9];
    const float* projw   = (const float*)d_in[10];
    const float* routerw = (const float*)d_in[11];
    const float* fc1     = (const float*)d_in[12];
    const float* fc2     = (const float*)d_in[13];
    const float* lmw     = (const float*)d_in[14];
    float* out = (float*)d_out;

    float* x   = sym(g_x);
    float* h   = sym(g_h);
    float* at  = sym(g_attn);
    float* qkv = sym(g_qkv);
    float* scs = sym(g_scores);
    float* hid = sym(g_hid);
    float* mp  = sym(g_mp);

    // embed + LN0
    embed_ln_kernel<<<M_, 256>>>(tokens, wte, wpe, n0g, n0b, x);

    for (int l = 0; l < L_; l++) {
        // LN1
        ln_kernel<<<M_, 256>>>(x, h, n1g + l * D_, n1b + l * D_);
        // QKV
        gemm_nt<0>(h, qkvw + (long)l * D3_ * D_, qkv, nullptr,
                   M_, D3_, D_, D_, D_, D3_, 0, D_);
        // scores = (Q K^T) / 8, batched over z=b*H+h, causal tile-skip
        {
            dim3 grid(T_ / 128, T_ / 128, B_ * H_);
            gemm_tile<0, true><<<grid, 256>>>(
                qkv, qkv + D_, scs, nullptr,
                T_, T_, HEAD_, D3_, D3_, T_,
                0, HEAD_, H_,
                (long)T_ * D3_, HEAD_, (long)T_ * D3_, HEAD_,
                (long)H_ * T_ * T_, (long)T_ * T_,
                0.125f, 1, 0);
        }
        // causal softmax
        softmax_kernel<<<B_ * H_ * T_, 256>>>(scs);
        // PV: out[b,h,i,:] = P V  (K truncated at causal tile boundary)
        {
            dim3 grid(1, T_ / 128, B_ * H_);
            gemm_tile<0, false><<<grid, 256>>>(
                scs, qkv + 2 * D_, at, nullptr,
                T_, HEAD_, T_, T_, D3_, D_,
                0, T_, H_,
                (long)H_ * T_ * T_, (long)T_ * T_, (long)T_ * D3_, HEAD_,
                (long)T_ * D_, HEAD_,
                1.f, 0, 1);
        }
        // x += attn @ proj^T
        gemm_nt<2>(at, projw + (long)l * D_ * D_, x, nullptr,
                   M_, D_, D_, D_, D_, D_, 0, D_);
        // LN2
        ln_kernel<<<M_, 256>>>(x, h, n2g + l * D_, n2b + l * D_);
        // router -> mp[token, e]
        router_kernel<<<M_, 256>>>(h, routerw + (long)l * E_ * D_, mp);
        // fc1 (all experts fused, N = 8*3072), epilogue: mp * relu(.)
        gemm_nt<1>(h, fc1 + (long)l * E_ * DFF_ * D_, hid, mp,
                   M_, E_ * DFF_, D_, D_, D_, E_ * DFF_, 0, D_);
        // x += fc2 (all experts fused via expert-strided K)
        gemm_nt<2>(hid, fc2 + (long)l * E_ * D_ * DFF_, x, nullptr,
                   M_, D_, E_ * DFF_, E_ * DFF_, DFF_, D_,
                   (long)D_ * DFF_, DFF_);
    }
    // logits
    gemm_nt<0>(x, lmw, out, nullptr, M_, V_, D_, D_, D_, V_, 0, D_);
}